// round 4
// baseline (speedup 1.0000x reference)
#include <cuda_runtime.h>
#include <cuda_bf16.h>

// ---------------------------------------------------------------------------
// TextGCN: 2-layer GCN.
//   dinv = rsqrt(deg) with self-loops (deg init = 1, += w at col)
//   layer: hs = (x @ W) * dinv ;  acc[i] = hs[i] + sum_{e: col=i} hs[row]*w
//          out = dinv * acc + b   (relu after layer 1)
// ---------------------------------------------------------------------------

#define N_NODES 100000
#define E_EDGES 3200000
#define HID 128
#define NCLS 16

// scratch (device globals: no allocation allowed)
__device__ int   g_row[E_EDGES];
__device__ int   g_col[E_EDGES];
__device__ int   g_is64;                     // edge_index dtype flag
__device__ __align__(16) float g_dinv[N_NODES];  // deg, then rsqrt in-place
__device__ __align__(16) float g_hs [(size_t)N_NODES * HID];
__device__ __align__(16) float g_acc[(size_t)N_NODES * HID];
__device__ __align__(16) float g_h2 [(size_t)N_NODES * NCLS];

__device__ __forceinline__ void red4(float* p, float a, float b, float c, float d) {
    asm volatile("red.global.add.v4.f32 [%0], {%1,%2,%3,%4};"
                 :: "l"(p), "f"(a), "f"(b), "f"(c), "f"(d) : "memory");
}

// ---------------------------------------------------------------------------
// Detect whether edge_index is int64 (odd int32 words all zero = high halves)
// or int32 (odd words are random node ids). One thread, 1024 samples.
__global__ void k_detect(const int* __restrict__ ei32) {
    if (threadIdx.x == 0 && blockIdx.x == 0) {
        int nz = 0;
        for (int i = 1; i < 2048; i += 2) nz |= (ei32[i] != 0);
        g_is64 = (nz == 0) ? 1 : 0;
    }
}

__global__ void k_init_deg() {
    int i = blockIdx.x * blockDim.x + threadIdx.x;
    if (i < N_NODES) g_dinv[i] = 1.0f;   // self-loop weight
}

__global__ void k_prep_edges(const int* __restrict__ ei32,
                             const float* __restrict__ ew) {
    int e = blockIdx.x * blockDim.x + threadIdx.x;
    if (e >= E_EDGES) return;
    int r, c;
    if (g_is64) {
        r = ei32[2 * (size_t)e];                       // low word, little endian
        c = ei32[2 * ((size_t)E_EDGES + e)];
    } else {
        r = ei32[e];
        c = ei32[(size_t)E_EDGES + e];
    }
    // defensive: invalid index -> self-referential no-op edge with zero weight
    if ((unsigned)r >= N_NODES) r = 0;
    if ((unsigned)c >= N_NODES) c = 0;
    g_row[e] = r;
    g_col[e] = c;
    atomicAdd(&g_dinv[c], ew[e]);
}

__global__ void k_rsqrt() {
    int i = blockIdx.x * blockDim.x + threadIdx.x;
    if (i < N_NODES) g_dinv[i] = rsqrtf(g_dinv[i]);  // deg >= 1 always
}

// ---------------------------------------------------------------------------
// GEMM1: hs = (A @ W) * dinv, also acc = hs (self-loop init).
// Block: 256 threads, tile 64 rows x 128 cols, full W1 (64KB) in smem.
__global__ void __launch_bounds__(256) k_gemm1(const float* __restrict__ A,
                                               const float* __restrict__ W) {
    extern __shared__ float sm[];
    float* Ws = sm;              // 128*128
    float* As = sm + 128 * 128;  // 64*128
    int tid = threadIdx.x;
    int bm  = blockIdx.x * 64;

    const float4* Wv  = (const float4*)W;
    float4*       Wsv = (float4*)Ws;
    #pragma unroll 4
    for (int i = tid; i < 128 * 32; i += 256) Wsv[i] = Wv[i];

    float4* Asv = (float4*)As;
    #pragma unroll 2
    for (int i = tid; i < 64 * 32; i += 256) {
        int r = bm + (i >> 5);
        float4 v = make_float4(0.f, 0.f, 0.f, 0.f);
        if (r < N_NODES) v = ((const float4*)A)[(size_t)r * 32 + (i & 31)];
        Asv[i] = v;
    }
    __syncthreads();

    int tx = tid & 31;   // col group: cols 4*tx..4*tx+3
    int ty = tid >> 5;   // row group: rows ty*8..ty*8+7

    float acc[8][4];
    #pragma unroll
    for (int i = 0; i < 8; i++)
        #pragma unroll
        for (int j = 0; j < 4; j++) acc[i][j] = 0.f;

    #pragma unroll 4
    for (int k = 0; k < 128; k++) {
        float4 b = ((const float4*)(Ws + k * 128))[tx];
        #pragma unroll
        for (int i = 0; i < 8; i++) {
            float a = As[(ty * 8 + i) * 128 + k];
            acc[i][0] += a * b.x;
            acc[i][1] += a * b.y;
            acc[i][2] += a * b.z;
            acc[i][3] += a * b.w;
        }
    }

    #pragma unroll
    for (int i = 0; i < 8; i++) {
        int r = bm + ty * 8 + i;
        if (r < N_NODES) {
            float d = g_dinv[r];
            float4 o = make_float4(acc[i][0] * d, acc[i][1] * d,
                                   acc[i][2] * d, acc[i][3] * d);
            ((float4*)(g_hs  + (size_t)r * 128))[tx] = o;
            ((float4*)(g_acc + (size_t)r * 128))[tx] = o;
        }
    }
}

// ---------------------------------------------------------------------------
// Scatter layer1: acc[col] += hs[row]*w, 128 floats/edge, 1 warp per edge.
// Warp loads 32 edges' metadata coalesced, then broadcasts via shuffle.
__global__ void __launch_bounds__(256) k_scatter128w(const float* __restrict__ ew) {
    const float* __restrict__ hs = g_hs;
    int lane  = threadIdx.x & 31;
    int warp  = (blockIdx.x * blockDim.x + threadIdx.x) >> 5;
    int nwarp = (gridDim.x * blockDim.x) >> 5;

    for (long long base = (long long)warp * 32; base < E_EDGES;
         base += (long long)nwarp * 32) {
        int e = (int)base + lane;
        int r = 0, c = 0; float wt = 0.f;
        if (e < E_EDGES) { r = g_row[e]; c = g_col[e]; wt = ew[e]; }
        int cnt = (int)min((long long)32, (long long)E_EDGES - base);
        for (int j = 0; j < cnt; j++) {
            int   rj = __shfl_sync(0xffffffffu, r, j);
            int   cj = __shfl_sync(0xffffffffu, c, j);
            float wj = __shfl_sync(0xffffffffu, wt, j);
            float4 v = __ldg(((const float4*)(hs + (size_t)rj * 128)) + lane);
            red4(g_acc + (size_t)cj * 128 + lane * 4,
                 v.x * wj, v.y * wj, v.z * wj, v.w * wj);
        }
    }
}

// Epilogue 1: x = relu(dinv*acc + b1), written into g_hs (reused as x).
__global__ void k_epi1(const float* __restrict__ b1) {
    int idx = blockIdx.x * blockDim.x + threadIdx.x;   // over N*32 float4
    if (idx >= N_NODES * 32) return;
    int i  = idx >> 5;
    int c4 = idx & 31;
    float d   = g_dinv[i];
    float4 v  = ((const float4*)g_acc)[idx];
    float4 bb = ((const float4*)b1)[c4];
    float4 o;
    o.x = fmaxf(v.x * d + bb.x, 0.f);
    o.y = fmaxf(v.y * d + bb.y, 0.f);
    o.z = fmaxf(v.z * d + bb.z, 0.f);
    o.w = fmaxf(v.w * d + bb.w, 0.f);
    ((float4*)g_hs)[idx] = o;
}

// ---------------------------------------------------------------------------
// GEMM2: hs2 = (x @ W2) * dinv  -> g_h2, and out init = hs2 (self loop).
__global__ void __launch_bounds__(256) k_gemm2(const float* __restrict__ W2,
                                               float* __restrict__ out) {
    __shared__ float W2s[128 * 16];   // 8 KB
    __shared__ float Xs[64 * 132];    // padded stride (bank-conflict free)
    int tid = threadIdx.x;
    int bm  = blockIdx.x * 64;

    for (int i = tid; i < 128 * 16 / 4; i += 256)
        ((float4*)W2s)[i] = ((const float4*)W2)[i];

    for (int i = tid; i < 64 * 32; i += 256) {
        int r  = i >> 5;
        int c4 = i & 31;
        float4 v = make_float4(0.f, 0.f, 0.f, 0.f);
        int gr = bm + r;
        if (gr < N_NODES) v = ((const float4*)g_hs)[(size_t)gr * 32 + c4];
        *(float4*)&Xs[r * 132 + c4 * 4] = v;
    }
    __syncthreads();

    int nl = tid >> 2;          // local node 0..63
    int cg = (tid & 3) * 4;     // col base
    float a0 = 0.f, a1 = 0.f, a2 = 0.f, a3 = 0.f;
    #pragma unroll 8
    for (int k = 0; k < 128; k++) {
        float  a = Xs[nl * 132 + k];
        float4 b = *(const float4*)&W2s[k * 16 + cg];
        a0 += a * b.x; a1 += a * b.y; a2 += a * b.z; a3 += a * b.w;
    }
    int r = bm + nl;
    if (r < N_NODES) {
        float d = g_dinv[r];
        float4 o = make_float4(a0 * d, a1 * d, a2 * d, a3 * d);
        ((float4*)(g_h2 + (size_t)r * 16))[tid & 3] = o;
        ((float4*)(out  + (size_t)r * 16))[tid & 3] = o;
    }
}

// Scatter layer2: out[col] += hs2[row]*w, 16 floats/edge, 1 thread per edge.
__global__ void k_scatter16(const float* __restrict__ ew, float* __restrict__ out) {
    int e = blockIdx.x * blockDim.x + threadIdx.x;
    if (e >= E_EDGES) return;
    int r = g_row[e], c = g_col[e];
    float wt = ew[e];
    const float4* src = (const float4*)(g_h2 + (size_t)r * 16);
    float* dst = out + (size_t)c * 16;
    #pragma unroll
    for (int j = 0; j < 4; j++) {
        float4 v = __ldg(src + j);
        red4(dst + j * 4, v.x * wt, v.y * wt, v.z * wt, v.w * wt);
    }
}

// Epilogue 2 (in-place on out): out = dinv*out + b2
__global__ void k_epi2(const float* __restrict__ b2, float* __restrict__ out) {
    int idx = blockIdx.x * blockDim.x + threadIdx.x;   // over N*4 float4
    if (idx >= N_NODES * 4) return;
    int i  = idx >> 2;
    int c4 = idx & 3;
    float d   = g_dinv[i];
    float4 v  = ((float4*)out)[idx];
    float4 bb = ((const float4*)b2)[c4];
    v.x = v.x * d + bb.x;
    v.y = v.y * d + bb.y;
    v.z = v.z * d + bb.z;
    v.w = v.w * d + bb.w;
    ((float4*)out)[idx] = v;
}

// ---------------------------------------------------------------------------
extern "C" void kernel_launch(void* const* d_in, const int* in_sizes, int n_in,
                              void* d_out, int out_size) {
    const int*   ei32 = (const int*)d_in[0];     // int32 or int64 (auto-detect)
    const float* ew   = (const float*)d_in[1];
    const float* emb  = (const float*)d_in[2];
    const float* W1   = (const float*)d_in[3];
    const float* b1   = (const float*)d_in[4];
    const float* W2   = (const float*)d_in[5];
    const float* b2   = (const float*)d_in[6];
    float*       out  = (float*)d_out;

    // Idempotent, non-stream API: legal during graph capture; no static guard.
    cudaFuncSetAttribute(k_gemm1, cudaFuncAttributeMaxDynamicSharedMemorySize,
                         (128 * 128 + 64 * 128) * sizeof(float));

    // dtype detect + degree / dinv
    k_detect<<<1, 32>>>(ei32);
    k_init_deg<<<(N_NODES + 255) / 256, 256>>>();
    k_prep_edges<<<(E_EDGES + 255) / 256, 256>>>(ei32, ew);
    k_rsqrt<<<(N_NODES + 255) / 256, 256>>>();

    // layer 1
    k_gemm1<<<(N_NODES + 63) / 64, 256,
              (128 * 128 + 64 * 128) * sizeof(float)>>>(emb, W1);
    k_scatter128w<<<2048, 256>>>(ew);
    k_epi1<<<(N_NODES * 32 + 255) / 256, 256>>>(b1);

    // layer 2
    k_gemm2<<<(N_NODES + 63) / 64, 256>>>(W2, out);
    k_scatter16<<<(E_EDGES + 255) / 256, 256>>>(ew, out);
    k_epi2<<<(N_NODES * 4 + 255) / 256, 256>>>(b2, out);
}

// round 5
// speedup vs baseline: 1.5658x; 1.5658x over previous
#include <cuda_runtime.h>
#include <cuda_bf16.h>

// ---------------------------------------------------------------------------
// TextGCN 2-layer GCN, CSR gather formulation.
//   dinv = rsqrt(1 + sum_{e:col=i} w_e)
//   hs   = (x @ W) * dinv
//   x'   = relu(dinv * (hs + sum_in hs[row]*w) + b)
// CSR (by destination col) built on-device each launch, shared by both layers.
// ---------------------------------------------------------------------------

#define N_NODES 100000
#define E_EDGES 3200000
#define HID 128
#define NCLS 16

#define SCAN_T 256
#define SCAN_V 4
#define SCAN_E (SCAN_T * SCAN_V)                       // 1024
#define SCAN_NB ((N_NODES + SCAN_E - 1) / SCAN_E)      // 98

// scratch (device globals: no allocation allowed)
__device__ int   g_is64;
__device__ int   g_deg [N_NODES];
__device__ int   g_off [N_NODES + 1];
__device__ int   g_cur [N_NODES];
__device__ int   g_bsum[SCAN_NB];
__device__ int   g_bpre[SCAN_NB];
__device__ __align__(16) int2  g_erec[E_EDGES];        // (row, bits(w)) dst-sorted
__device__ __align__(16) float g_dinv[N_NODES];
__device__ __align__(16) float g_hs [(size_t)N_NODES * HID];
__device__ __align__(16) float g_acc[(size_t)N_NODES * HID];
__device__ __align__(16) float g_h2 [(size_t)N_NODES * NCLS];

// ---------------------------------------------------------------------------
__global__ void k_detect(const int* __restrict__ ei32) {
    if (threadIdx.x == 0 && blockIdx.x == 0) {
        int nz = 0;
        for (int i = 1; i < 2048; i += 2) nz |= (ei32[i] != 0);
        g_is64 = (nz == 0) ? 1 : 0;
    }
}

__global__ void k_init() {
    int i = blockIdx.x * blockDim.x + threadIdx.x;
    if (i < N_NODES) { g_dinv[i] = 1.0f; g_deg[i] = 0; }
}

__device__ __forceinline__ void decode_edge(const int* __restrict__ ei32, int e,
                                            int& r, int& c) {
    if (g_is64) {
        r = ei32[2 * (size_t)e];
        c = ei32[2 * ((size_t)E_EDGES + e)];
    } else {
        r = ei32[e];
        c = ei32[(size_t)E_EDGES + e];
    }
    if ((unsigned)r >= N_NODES) r = 0;
    if ((unsigned)c >= N_NODES) c = 0;
}

__global__ void k_count(const int* __restrict__ ei32, const float* __restrict__ ew) {
    int e = blockIdx.x * blockDim.x + threadIdx.x;
    if (e >= E_EDGES) return;
    int r, c; decode_edge(ei32, e, r, c);
    atomicAdd(&g_deg[c], 1);
    atomicAdd(&g_dinv[c], ew[e]);
}

__global__ void k_rsqrt() {
    int i = blockIdx.x * blockDim.x + threadIdx.x;
    if (i < N_NODES) g_dinv[i] = rsqrtf(g_dinv[i]);
}

// --- prefix scan of g_deg -> exclusive offsets g_off -----------------------
__global__ void k_scan1() {
    __shared__ int sm[SCAN_T];
    int b = blockIdx.x, t = threadIdx.x;
    int base = b * SCAN_E + t * SCAN_V;
    int v[SCAN_V]; int s = 0;
    #pragma unroll
    for (int j = 0; j < SCAN_V; j++) {
        v[j] = (base + j < N_NODES) ? g_deg[base + j] : 0;
        s += v[j];
    }
    sm[t] = s; __syncthreads();
    for (int off = 1; off < SCAN_T; off <<= 1) {
        int x = (t >= off) ? sm[t - off] : 0;
        __syncthreads(); sm[t] += x; __syncthreads();
    }
    if (t == SCAN_T - 1) g_bsum[b] = sm[t];
    int run = (t > 0) ? sm[t - 1] : 0;
    #pragma unroll
    for (int j = 0; j < SCAN_V; j++) {
        if (base + j < N_NODES) g_off[base + j] = run;
        run += v[j];
    }
}
__global__ void k_scan2() {
    __shared__ int sm[128];
    int t = threadIdx.x;
    sm[t] = (t < SCAN_NB) ? g_bsum[t] : 0;
    __syncthreads();
    for (int off = 1; off < 128; off <<= 1) {
        int x = (t >= off) ? sm[t - off] : 0;
        __syncthreads(); sm[t] += x; __syncthreads();
    }
    if (t < SCAN_NB) g_bpre[t] = (t > 0) ? sm[t - 1] : 0;
}
__global__ void k_scan3() {
    int i = blockIdx.x * blockDim.x + threadIdx.x;
    if (i < N_NODES) {
        int o = g_off[i] + g_bpre[i / SCAN_E];
        g_off[i] = o;
        g_cur[i] = o;
    }
    if (i == 0) g_off[N_NODES] = E_EDGES;
}

__global__ void k_place(const int* __restrict__ ei32, const float* __restrict__ ew) {
    int e = blockIdx.x * blockDim.x + threadIdx.x;
    if (e >= E_EDGES) return;
    int r, c; decode_edge(ei32, e, r, c);
    int pos = atomicAdd(&g_cur[c], 1);
    g_erec[pos] = make_int2(r, __float_as_int(ew[e]));
}

// ---------------------------------------------------------------------------
// GEMM1: g_hs = (A @ W1) * dinv. W1 (64KB) + A tile in smem.
__global__ void __launch_bounds__(256) k_gemm1(const float* __restrict__ A,
                                               const float* __restrict__ W) {
    extern __shared__ float sm[];
    float* Ws = sm;              // 128*128
    float* As = sm + 128 * 128;  // 64*128
    int tid = threadIdx.x;
    int bm  = blockIdx.x * 64;

    const float4* Wv  = (const float4*)W;
    float4*       Wsv = (float4*)Ws;
    #pragma unroll 4
    for (int i = tid; i < 128 * 32; i += 256) Wsv[i] = Wv[i];

    float4* Asv = (float4*)As;
    #pragma unroll 2
    for (int i = tid; i < 64 * 32; i += 256) {
        int r = bm + (i >> 5);
        float4 v = make_float4(0.f, 0.f, 0.f, 0.f);
        if (r < N_NODES) v = ((const float4*)A)[(size_t)r * 32 + (i & 31)];
        Asv[i] = v;
    }
    __syncthreads();

    int tx = tid & 31;
    int ty = tid >> 5;

    float acc[8][4];
    #pragma unroll
    for (int i = 0; i < 8; i++)
        #pragma unroll
        for (int j = 0; j < 4; j++) acc[i][j] = 0.f;

    #pragma unroll 4
    for (int k = 0; k < 128; k++) {
        float4 b = ((const float4*)(Ws + k * 128))[tx];
        #pragma unroll
        for (int i = 0; i < 8; i++) {
            float a = As[(ty * 8 + i) * 128 + k];
            acc[i][0] += a * b.x;
            acc[i][1] += a * b.y;
            acc[i][2] += a * b.z;
            acc[i][3] += a * b.w;
        }
    }

    #pragma unroll
    for (int i = 0; i < 8; i++) {
        int r = bm + ty * 8 + i;
        if (r < N_NODES) {
            float d = g_dinv[r];
            ((float4*)(g_hs + (size_t)r * 128))[tx] =
                make_float4(acc[i][0] * d, acc[i][1] * d,
                            acc[i][2] * d, acc[i][3] * d);
        }
    }
}

// ---------------------------------------------------------------------------
// Layer-1 aggregation + epilogue: warp per node.
// x[i] = relu(dinv[i]*(hs[i] + sum_in hs[row]*w) + b1) -> g_acc
__global__ void __launch_bounds__(256) k_agg1(const float* __restrict__ b1) {
    int node = blockIdx.x * 8 + (threadIdx.x >> 5);
    if (node >= N_NODES) return;
    int lane = threadIdx.x & 31;
    const float4* hs4 = (const float4*)g_hs;

    float4 acc = hs4[(size_t)node * 32 + lane];      // self loop
    int e   = g_off[node];
    int end = g_off[node + 1];

    for (; e + 4 <= end; e += 4) {
        int2 a0 = g_erec[e],     a1 = g_erec[e + 1];
        int2 a2 = g_erec[e + 2], a3 = g_erec[e + 3];
        float4 v0 = __ldg(hs4 + (size_t)a0.x * 32 + lane);
        float4 v1 = __ldg(hs4 + (size_t)a1.x * 32 + lane);
        float4 v2 = __ldg(hs4 + (size_t)a2.x * 32 + lane);
        float4 v3 = __ldg(hs4 + (size_t)a3.x * 32 + lane);
        float w0 = __int_as_float(a0.y), w1 = __int_as_float(a1.y);
        float w2 = __int_as_float(a2.y), w3 = __int_as_float(a3.y);
        acc.x += v0.x * w0; acc.y += v0.y * w0; acc.z += v0.z * w0; acc.w += v0.w * w0;
        acc.x += v1.x * w1; acc.y += v1.y * w1; acc.z += v1.z * w1; acc.w += v1.w * w1;
        acc.x += v2.x * w2; acc.y += v2.y * w2; acc.z += v2.z * w2; acc.w += v2.w * w2;
        acc.x += v3.x * w3; acc.y += v3.y * w3; acc.z += v3.z * w3; acc.w += v3.w * w3;
    }
    for (; e < end; e++) {
        int2 a = g_erec[e];
        float4 v = __ldg(hs4 + (size_t)a.x * 32 + lane);
        float w = __int_as_float(a.y);
        acc.x += v.x * w; acc.y += v.y * w; acc.z += v.z * w; acc.w += v.w * w;
    }

    float d = g_dinv[node];
    float4 bb = ((const float4*)b1)[lane];
    float4 o;
    o.x = fmaxf(acc.x * d + bb.x, 0.f);
    o.y = fmaxf(acc.y * d + bb.y, 0.f);
    o.z = fmaxf(acc.z * d + bb.z, 0.f);
    o.w = fmaxf(acc.w * d + bb.w, 0.f);
    ((float4*)g_acc)[(size_t)node * 32 + lane] = o;
}

// ---------------------------------------------------------------------------
// GEMM2: g_h2 = (x @ W2) * dinv, x in g_acc.
__global__ void __launch_bounds__(256) k_gemm2(const float* __restrict__ W2) {
    __shared__ float W2s[128 * 16];
    __shared__ float Xs[64 * 132];
    int tid = threadIdx.x;
    int bm  = blockIdx.x * 64;

    for (int i = tid; i < 128 * 16 / 4; i += 256)
        ((float4*)W2s)[i] = ((const float4*)W2)[i];

    for (int i = tid; i < 64 * 32; i += 256) {
        int r  = i >> 5;
        int c4 = i & 31;
        float4 v = make_float4(0.f, 0.f, 0.f, 0.f);
        int gr = bm + r;
        if (gr < N_NODES) v = ((const float4*)g_acc)[(size_t)gr * 32 + c4];
        *(float4*)&Xs[r * 132 + c4 * 4] = v;
    }
    __syncthreads();

    int nl = tid >> 2;
    int cg = (tid & 3) * 4;
    float a0 = 0.f, a1 = 0.f, a2 = 0.f, a3 = 0.f;
    #pragma unroll 8
    for (int k = 0; k < 128; k++) {
        float  a = Xs[nl * 132 + k];
        float4 b = *(const float4*)&W2s[k * 16 + cg];
        a0 += a * b.x; a1 += a * b.y; a2 += a * b.z; a3 += a * b.w;
    }
    int r = bm + nl;
    if (r < N_NODES) {
        float d = g_dinv[r];
        ((float4*)(g_h2 + (size_t)r * 16))[tid & 3] =
            make_float4(a0 * d, a1 * d, a2 * d, a3 * d);
    }
}

// ---------------------------------------------------------------------------
// Layer-2 aggregation + epilogue: half-warp per node (16 lanes = 16 classes).
__global__ void __launch_bounds__(256) k_agg2(const float* __restrict__ b2,
                                              float* __restrict__ out) {
    int node = blockIdx.x * 16 + (threadIdx.x >> 4);
    if (node >= N_NODES) return;
    int l = threadIdx.x & 15;
    const float* h2 = g_h2;

    float acc = h2[(size_t)node * 16 + l];           // self loop
    int e   = g_off[node];
    int end = g_off[node + 1];

    for (; e + 4 <= end; e += 4) {
        int2 a0 = g_erec[e],     a1 = g_erec[e + 1];
        int2 a2 = g_erec[e + 2], a3 = g_erec[e + 3];
        float v0 = __ldg(h2 + (size_t)a0.x * 16 + l);
        float v1 = __ldg(h2 + (size_t)a1.x * 16 + l);
        float v2 = __ldg(h2 + (size_t)a2.x * 16 + l);
        float v3 = __ldg(h2 + (size_t)a3.x * 16 + l);
        acc += v0 * __int_as_float(a0.y);
        acc += v1 * __int_as_float(a1.y);
        acc += v2 * __int_as_float(a2.y);
        acc += v3 * __int_as_float(a3.y);
    }
    for (; e < end; e++) {
        int2 a = g_erec[e];
        acc += __ldg(h2 + (size_t)a.x * 16 + l) * __int_as_float(a.y);
    }

    out[(size_t)node * 16 + l] = g_dinv[node] * acc + b2[l];
}

// ---------------------------------------------------------------------------
extern "C" void kernel_launch(void* const* d_in, const int* in_sizes, int n_in,
                              void* d_out, int out_size) {
    const int*   ei32 = (const int*)d_in[0];
    const float* ew   = (const float*)d_in[1];
    const float* emb  = (const float*)d_in[2];
    const float* W1   = (const float*)d_in[3];
    const float* b1   = (const float*)d_in[4];
    const float* W2   = (const float*)d_in[5];
    const float* b2   = (const float*)d_in[6];
    float*       out  = (float*)d_out;

    cudaFuncSetAttribute(k_gemm1, cudaFuncAttributeMaxDynamicSharedMemorySize,
                         (128 * 128 + 64 * 128) * sizeof(float));

    // CSR build + dinv
    k_detect<<<1, 32>>>(ei32);
    k_init<<<(N_NODES + 255) / 256, 256>>>();
    k_count<<<(E_EDGES + 255) / 256, 256>>>(ei32, ew);
    k_rsqrt<<<(N_NODES + 255) / 256, 256>>>();
    k_scan1<<<SCAN_NB, SCAN_T>>>();
    k_scan2<<<1, 128>>>();
    k_scan3<<<(N_NODES + 255) / 256, 256>>>();
    k_place<<<(E_EDGES + 255) / 256, 256>>>(ei32, ew);

    // layer 1
    k_gemm1<<<(N_NODES + 63) / 64, 256,
              (128 * 128 + 64 * 128) * sizeof(float)>>>(emb, W1);
    k_agg1<<<(N_NODES + 7) / 8, 256>>>(b1);

    // layer 2
    k_gemm2<<<(N_NODES + 63) / 64, 256>>>(W2);
    k_agg2<<<(N_NODES + 15) / 16, 256>>>(b2, out);
}